// round 9
// baseline (speedup 1.0000x reference)
#include <cuda_runtime.h>

// MeshFit update_points_feat: per-class exact kNN (K=3) + softmax-weighted
// feature gather. C=4, N=4096, M=4096, D=32. Output (1, C*M, D) float32.
//
// R9: 16x16 grid, 16 LANES PER QUERY, 256 blocks x 1024 thr (2 blocks/SM ->
// ~full occupancy). Prep parallelized: count kernel (32 blocks, global
// atomics) + scatter kernel (32 blocks, per-block smem scan). Scratch
// counters are zero at module load and re-zeroed by the query kernel each
// launch (idempotent writes, no intra-kernel readers) -> deterministic on
// every replay. Bin/scatter order nondeterminism is harmless: all selection
// is lexicographic (d, idx), whose top-3 set is order-invariant => exact
// jax.lax.top_k semantics and bit-identical output.

#define CC    4
#define NV    4096
#define MV    4096
#define DF    32
#define GW    16
#define NCELL (GW * GW)
#define CELLW (1.0f / GW)
#define QL    16                 // lanes per query
#define TB    1024
#define QPB   (TB / QL)          // 64 queries per block
#define NBLK  ((CC * MV) / QPB)  // 256 blocks

__device__ float4 g_binned[CC][NV];           // (x, y, z, idx) in bin order
__device__ int    g_cellStart[CC][NCELL + 1];
__device__ int    g_qorder[CC][MV];           // query ids sorted by cell
__device__ int    g_counts[CC][NCELL];        // zeroed: load-time + query krnl
__device__ int    g_qcounts[CC][NCELL];
__device__ int    g_fill[CC][NCELL];          // zeroed by count kernel
__device__ int    g_qfill[CC][NCELL];

__device__ __forceinline__ int clampg(int v) {
    return v < 0 ? 0 : (v > GW - 1 ? GW - 1 : v);
}

__device__ __forceinline__ bool lex_lt(float t, int n, float d, int i) {
    return (t < d) || (t == d && n < i);
}

// Branchless sorted-top-3 insert with lexicographic (d, idx) order.
__device__ __forceinline__ void bl_insert(float t, int n,
                                          float& d0, float& d1, float& d2,
                                          int& i0, int& i1, int& i2)
{
    const bool c0 = lex_lt(t, n, d0, i0);
    const bool c1 = lex_lt(t, n, d1, i1);
    const bool c2 = lex_lt(t, n, d2, i2);
    d2 = c1 ? d1 : (c2 ? t : d2);  i2 = c1 ? i1 : (c2 ? n : i2);
    d1 = c0 ? d0 : (c1 ? t : d1);  i1 = c0 ? i0 : (c1 ? n : i1);
    d0 = c0 ? t  : d0;             i0 = c0 ? n  : i0;
}

// ---- K1: count cell populations (32 blocks: role x class x quarter) ------
__global__ void __launch_bounds__(256, 4)
count_kernel(const float* __restrict__ verts,
             const float* __restrict__ nverts)
{
    const int b = blockIdx.x;
    const int role = b & 1, c = (b >> 1) & 3, seg = b >> 3;
    const int tid = threadIdx.x;
    const int len = role ? MV : NV;
    const float* src = role ? (nverts + (size_t)c * MV * 3)
                            : (verts + (size_t)c * NV * 3);
    int* cnts = role ? g_qcounts[c] : g_counts[c];
    if (seg == 0) (role ? g_qfill : g_fill)[c][tid] = 0;   // tid < 256 = NCELL

    const int per = len / 4;
    for (int n = seg * per + tid; n < (seg + 1) * per; n += 256) {
        const int cx = clampg((int)(src[3 * n + 0] * GW));
        const int cy = clampg((int)(src[3 * n + 1] * GW));
        atomicAdd(&cnts[cy * GW + cx], 1);
    }
}

// ---- K2: scan + scatter (32 blocks, same mapping) ------------------------
__global__ void __launch_bounds__(256, 4)
scatter_kernel(const float* __restrict__ verts,
               const float* __restrict__ nverts)
{
    __shared__ int sc[NCELL];
    __shared__ int ex[NCELL];
    const int b = blockIdx.x;
    const int role = b & 1, c = (b >> 1) & 3, seg = b >> 3;
    const int tid = threadIdx.x;
    const int len = role ? MV : NV;
    const float* src = role ? (nverts + (size_t)c * MV * 3)
                            : (verts + (size_t)c * NV * 3);
    const int* cnts = role ? g_qcounts[c] : g_counts[c];

    const int my = cnts[tid];
    sc[tid] = my;
    __syncthreads();
#pragma unroll
    for (int st = 1; st < NCELL; st <<= 1) {
        const int add = (tid >= st) ? sc[tid - st] : 0;
        __syncthreads();
        sc[tid] += add;
        __syncthreads();
    }
    ex[tid] = sc[tid] - my;                     // exclusive prefix
    if (!role && seg == 0) {
        g_cellStart[c][tid] = ex[tid];
        if (tid == NCELL - 1) g_cellStart[c][NCELL] = sc[NCELL - 1];
    }
    __syncthreads();

    int* fill = role ? g_qfill[c] : g_fill[c];
    const int per = len / 4;
    for (int n = seg * per + tid; n < (seg + 1) * per; n += 256) {
        const float x = src[3 * n + 0], y = src[3 * n + 1];
        const int cell = clampg((int)(y * GW)) * GW + clampg((int)(x * GW));
        const int slot = ex[cell] + atomicAdd(&fill[cell], 1);
        if (role) {
            g_qorder[c][slot] = n;
        } else {
            g_binned[c][slot] = make_float4(x, y, src[3 * n + 2],
                                            __int_as_float(n));
        }
    }
}

// ---- K3: 16-lanes-per-query ring search ----------------------------------
__global__ void __launch_bounds__(TB, 2)
query_kernel(const float* __restrict__ feat,
             const float* __restrict__ nverts,
             float* __restrict__ out)
{
    extern __shared__ char smem[];
    float4* spts   = (float4*)smem;                      // 64 KB
    int*    sStart = (int*)(smem + NV * sizeof(float4)); // 257 ints

    const int tid = threadIdx.x;
    const int lq  = tid & (QL - 1);
    const int c    = blockIdx.x >> 6;          // 64 blocks per class
    const int slot = (blockIdx.x & 63) * QPB + (tid >> 4);

    // Re-zero scratch counters for the next launch (idempotent; these arrays
    // are not read anywhere in this kernel -> no ordering hazard).
    if (blockIdx.x < CC && tid < NCELL) g_counts[blockIdx.x][tid] = 0;
    if (blockIdx.x >= CC && blockIdx.x < 2 * CC && tid < NCELL)
        g_qcounts[blockIdx.x - CC][tid] = 0;

    // Stage this class's binned points + cell table.
    for (int i = tid; i < NV; i += TB) spts[i] = g_binned[c][i];
    for (int i = tid; i < NCELL + 1; i += TB) sStart[i] = g_cellStart[c][i];
    __syncthreads();

    const int m = g_qorder[c][slot];
    const float* q = nverts + ((size_t)c * MV + m) * 3;
    const float qx = q[0], qy = q[1], qz = q[2];
    const int cx = clampg((int)(qx * GW));
    const int cy = clampg((int)(qy * GW));

    float d0 = 3.402823466e38f, d1 = 3.402823466e38f, d2 = 3.402823466e38f;
    int   i0 = 0x7fffffff, i1 = 0x7fffffff, i2 = 0x7fffffff;

    bool done = false;
#pragma unroll 1
    for (int r = 0; r < GW; ++r) {
        if (!done) {
            const int y0 = cy - r < 0 ? 0 : cy - r;
            const int y1 = cy + r > GW - 1 ? GW - 1 : cy + r;
            const int x0 = cx - r < 0 ? 0 : cx - r;
            const int x1 = cx + r > GW - 1 ? GW - 1 : cx + r;
#pragma unroll 1
            for (int Y = y0; Y <= y1; ++Y) {
                const bool edge_y = (Y == cy - r) || (Y == cy + r);
#pragma unroll 1
                for (int X = x0; X <= x1; ++X) {
                    if (!edge_y && X != cx - r && X != cx + r) continue;
                    const int cell = Y * GW + X;
                    const int s = sStart[cell], e = sStart[cell + 1];
                    // 16 lanes of this query stride the cell's point list.
                    for (int p = s + lq; p < e; p += QL) {
                        const float4 pt = spts[p];
                        const float dx = qx - pt.x;
                        const float dy = qy - pt.y;
                        const float dz = qz - pt.z;
                        const float t = fmaf(dz, dz, fmaf(dy, dy, dx * dx));
                        bl_insert(t, __float_as_int(pt.w),
                                  d0, d1, d2, i0, i1, i2);
                    }
                }
            }
        }
        // Stop bound: B = min over the 16 lanes of local d2 (>= true d2).
        float B = d2;
#pragma unroll
        for (int off = 1; off < QL; off <<= 1)
            B = fminf(B, __shfl_xor_sync(0xffffffffu, B, off));
        const float sL = (cx - r <= 0)      ? 1e30f : qx - (cx - r) * CELLW;
        const float sR = (cx + r >= GW - 1) ? 1e30f : (cx + r + 1) * CELLW - qx;
        const float sB = (cy - r <= 0)      ? 1e30f : qy - (cy - r) * CELLW;
        const float sT = (cy + r >= GW - 1) ? 1e30f : (cy + r + 1) * CELLW - qy;
        const float dmin = fminf(fminf(sL, sR), fminf(sB, sT));
        done = done || (B * 1.00001f < dmin * dmin);
        if (__all_sync(0xffffffffu, done)) break;
    }

    // Butterfly merge across the 16 lanes; lex (d, idx) = exact top_k order.
#pragma unroll
    for (int off = 1; off < QL; off <<= 1) {
        const float pd0 = __shfl_xor_sync(0xffffffffu, d0, off);
        const float pd1 = __shfl_xor_sync(0xffffffffu, d1, off);
        const float pd2 = __shfl_xor_sync(0xffffffffu, d2, off);
        const int   pi0 = __shfl_xor_sync(0xffffffffu, i0, off);
        const int   pi1 = __shfl_xor_sync(0xffffffffu, i1, off);
        const int   pi2 = __shfl_xor_sync(0xffffffffu, i2, off);
        bl_insert(pd0, pi0, d0, d1, d2, i0, i1, i2);
        bl_insert(pd1, pi1, d0, d1, d2, i0, i1, i2);
        bl_insert(pd2, pi2, d0, d1, d2, i0, i1, i2);
    }

    // Global column indices + exact merge of constant-1.0 off-block fillers.
    const int base = c * NV;
    int g0 = base + i0, g1 = base + i1, g2 = base + i2;
    const int fbase = (c == 0) ? NV : 0;
#pragma unroll
    for (int k = 0; k < 3; ++k)
        bl_insert(1.0f, fbase + k, d0, d1, d2, g0, g1, g2);

    // softmax(-d), max-subtracted (d0 smallest).
    const float e1 = expf(d0 - d1);
    const float e2 = expf(d0 - d2);
    const float inv = 1.0f / (1.0f + e1 + e2);
    const float w0 = inv, w1 = e1 * inv, w2 = e2 * inv;

    // Lanes 0..7 of the group write the 8 float4 chunks of the output row.
    if (lq < DF / 4) {
        const float4 a  = ((const float4*)(feat + (size_t)g0 * DF))[lq];
        const float4 b  = ((const float4*)(feat + (size_t)g1 * DF))[lq];
        const float4 cv = ((const float4*)(feat + (size_t)g2 * DF))[lq];
        float4 rr;
        rr.x = w0 * a.x + w1 * b.x + w2 * cv.x;
        rr.y = w0 * a.y + w1 * b.y + w2 * cv.y;
        rr.z = w0 * a.z + w1 * b.z + w2 * cv.z;
        rr.w = w0 * a.w + w1 * b.w + w2 * cv.w;
        ((float4*)(out + ((size_t)c * MV + m) * DF))[lq] = rr;
    }
}

extern "C" void kernel_launch(void* const* d_in, const int* in_sizes, int n_in,
                              void* d_out, int out_size)
{
    const float* feat   = (const float*)d_in[0];  // (1, C*N, D)
    const float* verts  = (const float*)d_in[1];  // (C, N, 3)
    const float* nverts = (const float*)d_in[2];  // (C, M, 3)
    float* out = (float*)d_out;                   // (1, C*M, D)

    count_kernel<<<32, 256>>>(verts, nverts);
    scatter_kernel<<<32, 256>>>(verts, nverts);

    const int smem = NV * sizeof(float4) + (NCELL + 1) * sizeof(int);
    cudaFuncSetAttribute(query_kernel,
                         cudaFuncAttributeMaxDynamicSharedMemorySize, smem);
    query_kernel<<<NBLK, TB, smem>>>(feat, nverts, out);
}